// round 10
// baseline (speedup 1.0000x reference)
#include <cuda_runtime.h>
#include <math.h>

// Problem constants
#define B 256
#define N 256
#define D 512
#define EPSV 1e-8f

// R6 geometry (best measured): DSPLIT=8, 64-d chunks, 256 threads,
// 2 blocks/SM, 16 float4 register cache per thread (MLP=16).
#define DSPLIT 8
#define DCHUNK (D / DSPLIT)   // 64 d's per tile
#define DC4 (DCHUNK / 4)      // 16 float4 columns per tile
#define NGROUPS 16
#define NCHUNK (N / NGROUPS)  // 16 n-rows per thread
// block = DC4 * NGROUPS = 256 threads

#define D4 (D / 4)               // 128
#define PB4 ((N + D) * D4)       // new_pd float4 stride per batch = 98304
#define DIAG4 (N * D4)           // diag region offset within batch = 32768

#define NTILES (B * DSPLIT)      // 2048 tiles
#define PERSIST_BLOCKS (148 * 2) // one wave: 2 blocks per SM

// Persistent register-cached mega-kernel: 296 resident blocks grid-stride over
// all 2048 (b, h) tiles — no wave transitions, no block launch/retire ramps;
// pass-2 stores of tile t drain while tile t+1's loads issue.
// Per tile (R6 body):
//  Pass 1: load 128 KB pd slice into registers (abs-sum over n), interleaved
//          with zero-filling the tile's 128 KB diag share.
//  Reduce: lam/beta/delta per d; write new_central/new_err; patch 64 diagonal
//          scalars (ordered after zero-fill by the barrier).
//  Pass 2: scale register-resident values, store scaled_pd.
// pd is read from DRAM exactly once.
__global__ __launch_bounds__(256, 2) void k_mega(const float* __restrict__ cv,
                                                 const float4* __restrict__ pd4,
                                                 const float* __restrict__ err,
                                                 float* __restrict__ out_central,
                                                 float4* __restrict__ out_pd4,
                                                 float* __restrict__ out_err) {
    const int tid = threadIdx.x;
    const int d4 = tid & (DC4 - 1);  // 0..15 (float4 column within tile)
    const int g = tid >> 4;          // 0..15 (n-group)

    __shared__ float4 s_acc[NGROUPS][DC4];
    __shared__ float4 s_lam[DC4];

    const float4 z = make_float4(0.f, 0.f, 0.f, 0.f);

    for (int tile = blockIdx.x; tile < NTILES; tile += gridDim.x) {
        const int b = tile & (B - 1);  // tile % 256
        const int h = tile >> 8;       // tile / 256, 0..7

        // Base pointer for this thread's float4 column of the pd slice
        const float4* p = pd4 + (size_t)b * N * D4 + (size_t)(g * NCHUNK) * D4
                          + h * DC4 + d4;

        // Diag share of this tile: rows [h*64, h*64+64) of batch b
        // = 64 rows * 128 float4 = 8192 float4; zero-filled 512 float4/iter.
        float4* diag_blk = out_pd4 + (size_t)b * PB4 + DIAG4
                           + (size_t)h * DCHUNK * D4;

        // Pass 1: load slice into registers + abs-sum + diag zero-fill
        float4 v[NCHUNK];
        float4 acc = make_float4(0.f, 0.f, 0.f, 0.f);
#pragma unroll
        for (int n = 0; n < NCHUNK; n++) {
            v[n] = p[(size_t)n * D4];
            diag_blk[n * 512 + tid] = z;
            diag_blk[n * 512 + 256 + tid] = z;
            acc.x += fabsf(v[n].x);
            acc.y += fabsf(v[n].y);
            acc.z += fabsf(v[n].z);
            acc.w += fabsf(v[n].w);
        }
        // s_acc(i+1) writes are safe: all s_acc reads of iter i precede
        // barrier2(i), and this write follows barrier2(i) in program order.
        s_acc[g][d4] = acc;
        __syncthreads();  // barrier 1

        // Combine groups + compute lam/beta/delta: threads 0..63, one d each
        if (tid < DCHUNK) {
            const int dc4 = tid >> 2;
            const int lane = tid & 3;
            float r = 0.f;
#pragma unroll
            for (int gg = 0; gg < NGROUPS; gg++)
                r += ((const float*)&s_acc[gg][dc4])[lane];

            const int dg = h * DCHUNK + tid;  // global d index
            const int bd = b * D + dg;
            const float e = err[bd];
            const float c = cv[bd];

            const float radius = r + fabsf(e);
            const float lower = c - radius;
            const float upper = c + radius;
            const float rl = fmaxf(lower, 0.f);
            const float ru = fmaxf(upper, 0.f);

            float lam = (ru - rl) / (upper - lower + EPSV);
            if (lower >= 0.f) lam = 1.f;
            if (upper < 0.f) lam = 0.f;
            if (isnan(lam)) lam = 0.f;
            lam = fminf(fmaxf(lam, 0.f), 1.f);

            const float beta = (rl - lam * lower) * 0.5f;
            const float delta = fabsf(beta);

            out_central[bd] = lam * c + beta;
            out_err[bd] = lam * e;

            // Patch diagonal: local diag row tid has its element at global
            // col dg. Ordered after the zero-fill by barrier 1.
            ((float*)diag_blk)[(size_t)tid * D + dg] = delta;

            ((float*)&s_lam[dc4])[lane] = lam;
        }
        __syncthreads();  // barrier 2

        // Pass 2: scale register-resident values and store scaled_pd.
        // new_pd layout: (B, N+D, D); rows [0, N) are scaled_pd.
        const float4 lam4 = s_lam[d4];
        float4* o = out_pd4 + (size_t)b * PB4 + (size_t)(g * NCHUNK) * D4
                    + h * DC4 + d4;
#pragma unroll
        for (int n = 0; n < NCHUNK; n++) {
            float4 w;
            w.x = v[n].x * lam4.x;
            w.y = v[n].y * lam4.y;
            w.z = v[n].z * lam4.z;
            w.w = v[n].w * lam4.w;
            o[(size_t)n * D4] = w;
        }
    }
}

extern "C" void kernel_launch(void* const* d_in, const int* in_sizes, int n_in,
                              void* d_out, int out_size) {
    const float* cv = (const float*)d_in[0];   // (256, 512)
    const float* pd = (const float*)d_in[1];   // (256, 256, 512)
    const float* err = (const float*)d_in[2];  // (256, 512)

    float* out = (float*)d_out;
    // Output layout: [new_central (B*D)] [new_pd (B*(N+D)*D)] [new_err (B*D)]
    float* out_central = out;
    float* out_pd = out + (size_t)B * D;
    float* out_err = out + (size_t)B * D + (size_t)B * (N + D) * D;

    k_mega<<<PERSIST_BLOCKS, 256>>>(cv, (const float4*)pd, err,
                                    out_central, (float4*)out_pd, out_err);
}

// round 11
// speedup vs baseline: 1.1331x; 1.1331x over previous
#include <cuda_runtime.h>
#include <math.h>

// Problem constants
#define B 256
#define N 256
#define D 512
#define EPSV 1e-8f

// R6 geometry (best measured: 86.8 us total / 81.3 us kernel):
// DSPLIT=8, 64-d chunks, 256 threads, 2 blocks/SM, 16-float4 register cache.
#define DSPLIT 8
#define DCHUNK (D / DSPLIT)   // 64 d's per block
#define DC4 (DCHUNK / 4)      // 16 float4 columns per block
#define NGROUPS 16
#define NCHUNK (N / NGROUPS)  // 16 n-rows per thread
// block = DC4 * NGROUPS = 256 threads

#define D4 (D / 4)               // 128
#define PB4 ((N + D) * D4)       // new_pd float4 stride per batch = 98304
#define DIAG4 (N * D4)           // diag region offset within batch = 32768

// Register-cached mega-kernel (R6 body) with explicit issue ordering:
//  Pass 1a: front-batch all 16 slice loads (MLP=16).
//  Pass 1b: 32 independent diag zero-fill stores (hide load latency).
//  Pass 1c: abs-sum FMAs (consume loads, latency now covered).
//  Reduce:  lam/beta/delta per d (cv/err prefetched before barrier 1);
//           write new_central/new_err; patch 64 diagonal scalars.
//  Pass 2:  scale register-resident values, store scaled_pd.
//  pd is read from DRAM exactly once.
__global__ __launch_bounds__(256, 2) void k_mega(const float* __restrict__ cv,
                                                 const float4* __restrict__ pd4,
                                                 const float* __restrict__ err,
                                                 float* __restrict__ out_central,
                                                 float4* __restrict__ out_pd4,
                                                 float* __restrict__ out_err) {
    const int b = blockIdx.x;
    const int h = blockIdx.y;        // d-chunk index, 0..7
    const int tid = threadIdx.x;
    const int d4 = tid & (DC4 - 1);  // 0..15 (float4 column within chunk)
    const int g = tid >> 4;          // 0..15 (n-group)

    __shared__ float4 s_acc[NGROUPS][DC4];
    __shared__ float4 s_lam[DC4];

    // Base pointer for this thread's float4 column of the pd slice
    const float4* p = pd4 + (size_t)b * N * D4 + (size_t)(g * NCHUNK) * D4
                      + h * DC4 + d4;

    // Diag share of this block: rows [h*64, h*64+64) of batch b
    // = 64 rows * 128 float4 = 8192 float4.
    float4* diag_blk = out_pd4 + (size_t)b * PB4 + DIAG4 + (size_t)h * DCHUNK * D4;
    const float4 z = make_float4(0.f, 0.f, 0.f, 0.f);

    // Prefetch cv/err for the reduction threads (hides their DRAM latency
    // behind pass 1; only tid<64 uses them).
    const int dg = h * DCHUNK + tid;     // global d index (tid<64 range valid)
    const int bd = b * D + dg;
    float e_pf = 0.f, c_pf = 0.f;
    if (tid < DCHUNK) {
        e_pf = err[bd];
        c_pf = cv[bd];
    }

    // Pass 1a: front-batch all 16 loads
    float4 v[NCHUNK];
#pragma unroll
    for (int n = 0; n < NCHUNK; n++)
        v[n] = p[(size_t)n * D4];

    // Pass 1b: diag zero-fill (independent stores; cover load latency)
#pragma unroll
    for (int n = 0; n < NCHUNK; n++) {
        diag_blk[n * 512 + tid] = z;
        diag_blk[n * 512 + 256 + tid] = z;
    }

    // Pass 1c: abs-sum
    float4 acc = make_float4(0.f, 0.f, 0.f, 0.f);
#pragma unroll
    for (int n = 0; n < NCHUNK; n++) {
        acc.x += fabsf(v[n].x);
        acc.y += fabsf(v[n].y);
        acc.z += fabsf(v[n].z);
        acc.w += fabsf(v[n].w);
    }
    s_acc[g][d4] = acc;
    __syncthreads();  // barrier 1

    // Combine groups + compute lam/beta/delta: threads 0..63, one d each
    if (tid < DCHUNK) {
        const int dc4 = tid >> 2;
        const int lane = tid & 3;
        float r = 0.f;
#pragma unroll
        for (int gg = 0; gg < NGROUPS; gg++)
            r += ((const float*)&s_acc[gg][dc4])[lane];

        const float e = e_pf;
        const float c = c_pf;

        const float radius = r + fabsf(e);
        const float lower = c - radius;
        const float upper = c + radius;
        const float rl = fmaxf(lower, 0.f);
        const float ru = fmaxf(upper, 0.f);

        float lam = (ru - rl) / (upper - lower + EPSV);
        if (lower >= 0.f) lam = 1.f;
        if (upper < 0.f) lam = 0.f;
        if (isnan(lam)) lam = 0.f;
        lam = fminf(fmaxf(lam, 0.f), 1.f);

        const float beta = (rl - lam * lower) * 0.5f;
        const float delta = fabsf(beta);

        out_central[bd] = lam * c + beta;
        out_err[bd] = lam * e;

        // Patch diagonal: local diag row tid has its element at global col dg.
        // Ordered after the zero-fill by barrier 1.
        ((float*)diag_blk)[(size_t)tid * D + dg] = delta;

        ((float*)&s_lam[dc4])[lane] = lam;
    }
    __syncthreads();  // barrier 2

    // Pass 2: scale register-resident values and store scaled_pd.
    // new_pd layout: (B, N+D, D); rows [0, N) are scaled_pd.
    const float4 lam4 = s_lam[d4];
    float4* o = out_pd4 + (size_t)b * PB4 + (size_t)(g * NCHUNK) * D4
                + h * DC4 + d4;
#pragma unroll
    for (int n = 0; n < NCHUNK; n++) {
        float4 w;
        w.x = v[n].x * lam4.x;
        w.y = v[n].y * lam4.y;
        w.z = v[n].z * lam4.z;
        w.w = v[n].w * lam4.w;
        o[(size_t)n * D4] = w;
    }
}

extern "C" void kernel_launch(void* const* d_in, const int* in_sizes, int n_in,
                              void* d_out, int out_size) {
    const float* cv = (const float*)d_in[0];   // (256, 512)
    const float* pd = (const float*)d_in[1];   // (256, 256, 512)
    const float* err = (const float*)d_in[2];  // (256, 512)

    float* out = (float*)d_out;
    // Output layout: [new_central (B*D)] [new_pd (B*(N+D)*D)] [new_err (B*D)]
    float* out_central = out;
    float* out_pd = out + (size_t)B * D;
    float* out_err = out + (size_t)B * D + (size_t)B * (N + D) * D;

    dim3 grid(B, DSPLIT);  // 2048 blocks of 256 threads
    k_mega<<<grid, 256>>>(cv, (const float4*)pd, err,
                          out_central, (float4*)out_pd, out_err);
}

// round 12
// speedup vs baseline: 1.1365x; 1.0030x over previous
#include <cuda_runtime.h>
#include <math.h>

// Problem constants
#define B 256
#define N 256
#define D 512
#define EPSV 1e-8f

// Champion geometry (R6/R11, 86.8 us): DSPLIT=8, 64-d chunks, 256 threads,
// 2 blocks/SM, 16-float4 register cache per thread (MLP=16).
#define DSPLIT 8
#define DCHUNK (D / DSPLIT)   // 64 d's per block
#define DC4 (DCHUNK / 4)      // 16 float4 columns per block
#define NGROUPS 16
#define NCHUNK (N / NGROUPS)  // 16 n-rows per thread
// block = DC4 * NGROUPS = 256 threads

#define D4 (D / 4)               // 128
#define PB4 ((N + D) * D4)       // new_pd float4 stride per batch = 98304
#define DIAG4 (N * D4)           // diag region offset within batch = 32768

// Register-cached mega-kernel (champion body), stores-first ramp:
//  Pass 1a: diag zero-fill stores FIRST (commit immediately at block start,
//           filling the DRAM write path while the load queue spins up).
//  Pass 1b: front-batch all 16 slice loads (MLP=16).
//  Pass 1c: abs-sum FMAs.
//  Reduce:  lam/beta/delta per d (cv/err prefetched before barrier 1);
//           write new_central/new_err; patch 64 diagonal scalars.
//  Pass 2:  scale register-resident values, store scaled_pd.
//  pd is read from DRAM exactly once.
__global__ __launch_bounds__(256, 2) void k_mega(const float* __restrict__ cv,
                                                 const float4* __restrict__ pd4,
                                                 const float* __restrict__ err,
                                                 float* __restrict__ out_central,
                                                 float4* __restrict__ out_pd4,
                                                 float* __restrict__ out_err) {
    const int b = blockIdx.x;
    const int h = blockIdx.y;        // d-chunk index, 0..7
    const int tid = threadIdx.x;
    const int d4 = tid & (DC4 - 1);  // 0..15 (float4 column within chunk)
    const int g = tid >> 4;          // 0..15 (n-group)

    __shared__ float4 s_acc[NGROUPS][DC4];
    __shared__ float4 s_lam[DC4];

    // Base pointer for this thread's float4 column of the pd slice
    const float4* p = pd4 + (size_t)b * N * D4 + (size_t)(g * NCHUNK) * D4
                      + h * DC4 + d4;

    // Diag share of this block: rows [h*64, h*64+64) of batch b
    // = 64 rows * 128 float4 = 8192 float4.
    float4* diag_blk = out_pd4 + (size_t)b * PB4 + DIAG4 + (size_t)h * DCHUNK * D4;
    const float4 z = make_float4(0.f, 0.f, 0.f, 0.f);

    // Pass 1a: diag zero-fill first — stores commit immediately.
#pragma unroll
    for (int n = 0; n < NCHUNK; n++) {
        diag_blk[n * 512 + tid] = z;
        diag_blk[n * 512 + 256 + tid] = z;
    }

    // Prefetch cv/err for the reduction threads (hidden behind pass 1).
    const int dg = h * DCHUNK + tid;     // global d index (valid for tid<64)
    const int bd = b * D + dg;
    float e_pf = 0.f, c_pf = 0.f;
    if (tid < DCHUNK) {
        e_pf = err[bd];
        c_pf = cv[bd];
    }

    // Pass 1b: front-batch all 16 loads
    float4 v[NCHUNK];
#pragma unroll
    for (int n = 0; n < NCHUNK; n++)
        v[n] = p[(size_t)n * D4];

    // Pass 1c: abs-sum
    float4 acc = make_float4(0.f, 0.f, 0.f, 0.f);
#pragma unroll
    for (int n = 0; n < NCHUNK; n++) {
        acc.x += fabsf(v[n].x);
        acc.y += fabsf(v[n].y);
        acc.z += fabsf(v[n].z);
        acc.w += fabsf(v[n].w);
    }
    s_acc[g][d4] = acc;
    __syncthreads();  // barrier 1

    // Combine groups + compute lam/beta/delta: threads 0..63, one d each
    if (tid < DCHUNK) {
        const int dc4 = tid >> 2;
        const int lane = tid & 3;
        float r = 0.f;
#pragma unroll
        for (int gg = 0; gg < NGROUPS; gg++)
            r += ((const float*)&s_acc[gg][dc4])[lane];

        const float e = e_pf;
        const float c = c_pf;

        const float radius = r + fabsf(e);
        const float lower = c - radius;
        const float upper = c + radius;
        const float rl = fmaxf(lower, 0.f);
        const float ru = fmaxf(upper, 0.f);

        float lam = (ru - rl) / (upper - lower + EPSV);
        if (lower >= 0.f) lam = 1.f;
        if (upper < 0.f) lam = 0.f;
        if (isnan(lam)) lam = 0.f;
        lam = fminf(fmaxf(lam, 0.f), 1.f);

        const float beta = (rl - lam * lower) * 0.5f;
        const float delta = fabsf(beta);

        out_central[bd] = lam * c + beta;
        out_err[bd] = lam * e;

        // Patch diagonal: local diag row tid has its element at global col dg.
        // Ordered after the zero-fill by barrier 1.
        ((float*)diag_blk)[(size_t)tid * D + dg] = delta;

        ((float*)&s_lam[dc4])[lane] = lam;
    }
    __syncthreads();  // barrier 2

    // Pass 2: scale register-resident values and store scaled_pd.
    // new_pd layout: (B, N+D, D); rows [0, N) are scaled_pd.
    const float4 lam4 = s_lam[d4];
    float4* o = out_pd4 + (size_t)b * PB4 + (size_t)(g * NCHUNK) * D4
                + h * DC4 + d4;
#pragma unroll
    for (int n = 0; n < NCHUNK; n++) {
        float4 w;
        w.x = v[n].x * lam4.x;
        w.y = v[n].y * lam4.y;
        w.z = v[n].z * lam4.z;
        w.w = v[n].w * lam4.w;
        o[(size_t)n * D4] = w;
    }
}

extern "C" void kernel_launch(void* const* d_in, const int* in_sizes, int n_in,
                              void* d_out, int out_size) {
    const float* cv = (const float*)d_in[0];   // (256, 512)
    const float* pd = (const float*)d_in[1];   // (256, 256, 512)
    const float* err = (const float*)d_in[2];  // (256, 512)

    float* out = (float*)d_out;
    // Output layout: [new_central (B*D)] [new_pd (B*(N+D)*D)] [new_err (B*D)]
    float* out_central = out;
    float* out_pd = out + (size_t)B * D;
    float* out_err = out + (size_t)B * D + (size_t)B * (N + D) * D;

    dim3 grid(B, DSPLIT);  // 2048 blocks of 256 threads
    k_mega<<<grid, 256>>>(cv, (const float4*)pd, err,
                          out_central, (float4*)out_pd, out_err);
}

// round 13
// speedup vs baseline: 1.1381x; 1.0015x over previous
#include <cuda_runtime.h>
#include <math.h>

// Problem constants
#define B 256
#define N 256
#define D 512
#define EPSV 1e-8f

// Champion geometry (R6/R11/R12, 86.5 us): DSPLIT=8, 64-d chunks, 256
// threads, 2 blocks/SM, 16-float4 register cache per thread (MLP=16).
#define DSPLIT 8
#define DCHUNK (D / DSPLIT)   // 64 d's per block
#define DC4 (DCHUNK / 4)      // 16 float4 columns per block
#define NGROUPS 16
#define NCHUNK (N / NGROUPS)  // 16 n-rows per thread
// block = DC4 * NGROUPS = 256 threads

#define D4 (D / 4)               // 128
#define PB4 ((N + D) * D4)       // new_pd float4 stride per batch = 98304
#define DIAG4 (N * D4)           // diag region offset within batch = 32768

// Register-cached mega-kernel (champion body) with PARITY-STAGGERED pass-1:
// the two co-resident blocks per SM start in opposite phases (one issuing
// its diag zero-fill stores while the other issues its slice loads), so the
// SM presents a steady mixed read/write stream to DRAM instead of
// oscillating between all-read and all-write windows.
//  Pass 1 (order depends on blockIdx parity):
//    - diag zero-fill stores (32 independent STG.128)
//    - front-batched 16 slice loads (MLP=16)
//    then abs-sum FMAs.
//  Reduce: lam/beta/delta per d (cv/err prefetched); write new_central /
//          new_err; patch 64 diagonal scalars (ordered by barrier 1).
//  Pass 2: scale register-resident values, store scaled_pd.
//  pd is read from DRAM exactly once.
__global__ __launch_bounds__(256, 2) void k_mega(const float* __restrict__ cv,
                                                 const float4* __restrict__ pd4,
                                                 const float* __restrict__ err,
                                                 float* __restrict__ out_central,
                                                 float4* __restrict__ out_pd4,
                                                 float* __restrict__ out_err) {
    const int b = blockIdx.x;
    const int h = blockIdx.y;        // d-chunk index, 0..7
    const int tid = threadIdx.x;
    const int d4 = tid & (DC4 - 1);  // 0..15 (float4 column within chunk)
    const int g = tid >> 4;          // 0..15 (n-group)

    __shared__ float4 s_acc[NGROUPS][DC4];
    __shared__ float4 s_lam[DC4];

    // Base pointer for this thread's float4 column of the pd slice
    const float4* p = pd4 + (size_t)b * N * D4 + (size_t)(g * NCHUNK) * D4
                      + h * DC4 + d4;

    // Diag share of this block: rows [h*64, h*64+64) of batch b
    // = 64 rows * 128 float4 = 8192 float4.
    float4* diag_blk = out_pd4 + (size_t)b * PB4 + DIAG4 + (size_t)h * DCHUNK * D4;
    const float4 z = make_float4(0.f, 0.f, 0.f, 0.f);

    // Prefetch cv/err for the reduction threads (hidden behind pass 1).
    const int dg = h * DCHUNK + tid;     // global d index (valid for tid<64)
    const int bd = b * D + dg;
    float e_pf = 0.f, c_pf = 0.f;
    if (tid < DCHUNK) {
        e_pf = err[bd];
        c_pf = cv[bd];
    }

    float4 v[NCHUNK];
    if (b & 1) {
        // Odd blocks: stores first, then loads.
#pragma unroll
        for (int n = 0; n < NCHUNK; n++) {
            diag_blk[n * 512 + tid] = z;
            diag_blk[n * 512 + 256 + tid] = z;
        }
#pragma unroll
        for (int n = 0; n < NCHUNK; n++)
            v[n] = p[(size_t)n * D4];
    } else {
        // Even blocks: loads first, then stores.
#pragma unroll
        for (int n = 0; n < NCHUNK; n++)
            v[n] = p[(size_t)n * D4];
#pragma unroll
        for (int n = 0; n < NCHUNK; n++) {
            diag_blk[n * 512 + tid] = z;
            diag_blk[n * 512 + 256 + tid] = z;
        }
    }

    // Abs-sum
    float4 acc = make_float4(0.f, 0.f, 0.f, 0.f);
#pragma unroll
    for (int n = 0; n < NCHUNK; n++) {
        acc.x += fabsf(v[n].x);
        acc.y += fabsf(v[n].y);
        acc.z += fabsf(v[n].z);
        acc.w += fabsf(v[n].w);
    }
    s_acc[g][d4] = acc;
    __syncthreads();  // barrier 1

    // Combine groups + compute lam/beta/delta: threads 0..63, one d each
    if (tid < DCHUNK) {
        const int dc4 = tid >> 2;
        const int lane = tid & 3;
        float r = 0.f;
#pragma unroll
        for (int gg = 0; gg < NGROUPS; gg++)
            r += ((const float*)&s_acc[gg][dc4])[lane];

        const float e = e_pf;
        const float c = c_pf;

        const float radius = r + fabsf(e);
        const float lower = c - radius;
        const float upper = c + radius;
        const float rl = fmaxf(lower, 0.f);
        const float ru = fmaxf(upper, 0.f);

        float lam = (ru - rl) / (upper - lower + EPSV);
        if (lower >= 0.f) lam = 1.f;
        if (upper < 0.f) lam = 0.f;
        if (isnan(lam)) lam = 0.f;
        lam = fminf(fmaxf(lam, 0.f), 1.f);

        const float beta = (rl - lam * lower) * 0.5f;
        const float delta = fabsf(beta);

        out_central[bd] = lam * c + beta;
        out_err[bd] = lam * e;

        // Patch diagonal: local diag row tid has its element at global col dg.
        // Ordered after the zero-fill by barrier 1.
        ((float*)diag_blk)[(size_t)tid * D + dg] = delta;

        ((float*)&s_lam[dc4])[lane] = lam;
    }
    __syncthreads();  // barrier 2

    // Pass 2: scale register-resident values and store scaled_pd.
    // new_pd layout: (B, N+D, D); rows [0, N) are scaled_pd.
    const float4 lam4 = s_lam[d4];
    float4* o = out_pd4 + (size_t)b * PB4 + (size_t)(g * NCHUNK) * D4
                + h * DC4 + d4;
#pragma unroll
    for (int n = 0; n < NCHUNK; n++) {
        float4 w;
        w.x = v[n].x * lam4.x;
        w.y = v[n].y * lam4.y;
        w.z = v[n].z * lam4.z;
        w.w = v[n].w * lam4.w;
        o[(size_t)n * D4] = w;
    }
}

extern "C" void kernel_launch(void* const* d_in, const int* in_sizes, int n_in,
                              void* d_out, int out_size) {
    const float* cv = (const float*)d_in[0];   // (256, 512)
    const float* pd = (const float*)d_in[1];   // (256, 256, 512)
    const float* err = (const float*)d_in[2];  // (256, 512)

    float* out = (float*)d_out;
    // Output layout: [new_central (B*D)] [new_pd (B*(N+D)*D)] [new_err (B*D)]
    float* out_central = out;
    float* out_pd = out + (size_t)B * D;
    float* out_err = out + (size_t)B * D + (size_t)B * (N + D) * D;

    dim3 grid(B, DSPLIT);  // 2048 blocks of 256 threads
    k_mega<<<grid, 256>>>(cv, (const float4*)pd, err,
                          out_central, (float4*)out_pd, out_err);
}